// round 3
// baseline (speedup 1.0000x reference)
#include <cuda_runtime.h>

#define FULL 0xffffffffu

constexpr int NS   = 32;     // samples per batch
constexpr int H1   = 16;
constexpr int BASE = 32;
constexpr int OUTD = 13;
constexpr int DIN  = 79;     // 3 + 64 + 12
constexpr float EPS = 1e-6f;

constexpr int WARPS_PER_BLOCK = 4;
constexpr int XZ_STRIDE = 68;          // 64 + 4 pad floats; 272B, 16B-aligned, conflict-free

// ---- packed f32x2 helpers (sm_100+ PTX) ------------------------------------
__device__ __forceinline__ unsigned long long pk2(float a, float b) {
    unsigned long long r;
    asm("mov.b64 %0, {%1, %2};" : "=l"(r) : "f"(a), "f"(b));
    return r;
}
__device__ __forceinline__ unsigned long long bcast2(float a) {
    unsigned long long r;
    asm("mov.b64 %0, {%1, %1};" : "=l"(r) : "f"(a));
    return r;
}
__device__ __forceinline__ void upk2(unsigned long long v, float& a, float& b) {
    asm("mov.b64 {%0, %1}, %2;" : "=f"(a), "=f"(b) : "l"(v));
}
__device__ __forceinline__ void fma2(unsigned long long& d,
                                     unsigned long long a, unsigned long long b) {
    asm("fma.rn.f32x2 %0, %1, %2, %0;" : "+l"(d) : "l"(a), "l"(b));
}

// h[0..7] += x * w1row (16 outputs = 8 f32x2 pairs), weights broadcast from smem.
__device__ __forceinline__ void row_fma(unsigned long long (&h)[8], float x,
                                        const ulonglong2* __restrict__ wq, int row) {
    unsigned long long bx = bcast2(x);
    ulonglong2 p0 = wq[row * 4 + 0];
    ulonglong2 p1 = wq[row * 4 + 1];
    ulonglong2 p2 = wq[row * 4 + 2];
    ulonglong2 p3 = wq[row * 4 + 3];
    fma2(h[0], bx, p0.x); fma2(h[1], bx, p0.y);
    fma2(h[2], bx, p1.x); fma2(h[3], bx, p1.y);
    fma2(h[4], bx, p2.x); fma2(h[5], bx, p2.y);
    fma2(h[6], bx, p3.x); fma2(h[7], bx, p3.y);
}

__device__ __forceinline__ float wsum(float v) {
    #pragma unroll
    for (int o = 16; o > 0; o >>= 1) v += __shfl_xor_sync(FULL, v, o);
    return v;
}

__global__ __launch_bounds__(WARPS_PER_BLOCK * 32) void plane_kernel(
    const float* __restrict__ pos,  const float* __restrict__ quat,
    const float* __restrict__ xz,   const float* __restrict__ aabb,
    const int*   __restrict__ widx, const float* __restrict__ pls_p,
    const float* __restrict__ w1,   const float* __restrict__ b1,
    const float* __restrict__ g1,   const float* __restrict__ be1,
    const float* __restrict__ w2a,  const float* __restrict__ b2a,
    const float* __restrict__ g2a,  const float* __restrict__ be2a,
    const float* __restrict__ w2b,  const float* __restrict__ b2b,
    const float* __restrict__ g2b,  const float* __restrict__ be2b,
    const float* __restrict__ wout, const float* __restrict__ bout,
    float* __restrict__ out)
{
    // stage-1 weights only in smem (hot, broadcast-read 268x per warp)
    __shared__ __align__(16) float s_w1[DIN * H1];              // 79 x 16 = 5056 B
    __shared__ float s_b1[H1], s_g1[H1], s_be1[H1];
    // per-warp coalesced gather staging: 32 rows x 68 floats (padded stride)
    __shared__ __align__(16) float s_xz[WARPS_PER_BLOCK][NS * XZ_STRIDE];  // 4 x 8704 B

    const int t = threadIdx.x;
    for (int i = t; i < DIN * H1; i += WARPS_PER_BLOCK * 32) s_w1[i] = w1[i];
    if (t < H1) { s_b1[t] = b1[t]; s_g1[t] = g1[t]; s_be1[t] = be1[t]; }
    __syncthreads();

    const int wid  = t >> 5;
    const int lane = t & 31;
    const int b    = blockIdx.x * WARPS_PER_BLOCK + wid;   // one warp per batch

    // --- issue the gather FIRST so DRAM latency overlaps the scalar math below ---
    const int idx = widx[NS * b + lane];                 // 0..511 (per-sample, lane = s)
    {
        // iteration i: lanes 0-15 load row 2i, lanes 16-31 load row 2i+1
        // (4 distinct 128B lines per LDG.128 instead of 32 for a per-lane scatter)
        float* buf = s_xz[wid];
        const float* xzb = xz + (size_t)b * 512 * 64;
        #pragma unroll
        for (int i = 0; i < 16; i++) {
            const int f  = i * 32 + lane;       // float4 slot 0..511
            const int r  = f >> 4;              // row 0..31
            const int c4 = f & 15;              // float4 column 0..15
            const int ridx = __shfl_sync(FULL, idx, r);
            const float4 v = *(reinterpret_cast<const float4*>(xzb + (size_t)ridx * 64) + c4);
            *reinterpret_cast<float4*>(buf + r * XZ_STRIDE + c4 * 4) = v;
        }
    }

    // --- per-batch scalars (broadcast loads; independent of the gather, overlaps it) ---
    float qx = quat[4*b+0], qy = quat[4*b+1], qz = quat[4*b+2], qw = quat[4*b+3];
    const float qn = rsqrtf(qx*qx + qy*qy + qz*qz + qw*qw);
    qx *= qn; qy *= qn; qz *= qn; qw *= qn;
    const float R00 = 1.f - 2.f*(qy*qy + qz*qz), R01 = 2.f*(qx*qy - qz*qw), R02 = 2.f*(qx*qz + qy*qw);
    const float R10 = 2.f*(qx*qy + qz*qw), R11 = 1.f - 2.f*(qx*qx + qz*qz), R12 = 2.f*(qy*qz - qx*qw);
    const float R20 = 2.f*(qx*qz - qy*qw), R21 = 2.f*(qy*qz + qx*qw), R22 = 1.f - 2.f*(qx*qx + qy*qy);
    const float px = pos[3*b+0], py = pos[3*b+1], pz = pos[3*b+2];
    const float es = expf(pls_p[0]);
    const float lo0 = aabb[6*b+0], lo1 = aabb[6*b+1], lo2 = aabb[6*b+2];
    const float sd0 = (aabb[6*b+3] - lo0) * 0.125f;
    const float sd1 = (aabb[6*b+4] - lo1) * 0.125f;
    const float sd2 = (aabb[6*b+5] - lo2) * 0.125f;

    // --- per-sample voxel center, rotated + translated (meshgrid 'ij' decode) ---
    const float c0 = (float)((idx >> 6) & 7) + 0.5f;     // i
    const float c1 = (float)((idx >> 3) & 7) + 0.5f;     // j
    const float c2 = (float)( idx       & 7) + 0.5f;     // k
    const float v0 = c0 * sd0 + lo0;
    const float v1 = c1 * sd1 + lo1;
    const float v2 = c2 * sd2 + lo2;
    const float pk0 = R00*v0 + R01*v1 + R02*v2 + px;
    const float pk1 = R10*v0 + R11*v1 + R12*v2 + py;
    const float pk2v= R20*v0 + R21*v1 + R22*v2 + pz;

    // pose-part of stage-1 (identical across lanes): compute on lanes 0..15 only
    float pc = 0.f;
    if (lane < H1) {
        const float pose[12] = { px*es, py*es, pz*es,
                                 R00, R01, R02, R10, R11, R12, R20, R21, R22 };
        pc = s_b1[lane];
        #pragma unroll
        for (int m = 0; m < 12; m++) pc += pose[m] * s_w1[(67 + m) * H1 + lane];
    }

    unsigned long long h[8];
    #pragma unroll
    for (int p = 0; p < 8; p++) {
        float a = __shfl_sync(FULL, pc, 2 * p);
        float c = __shfl_sync(FULL, pc, 2 * p + 1);
        h[p] = pk2(a, c);
    }

    const ulonglong2* wq = reinterpret_cast<const ulonglong2*>(s_w1);
    row_fma(h, pk0,  wq, 0);
    row_fma(h, pk1,  wq, 1);
    row_fma(h, pk2v, wq, 2);

    __syncwarp();   // gather STS of this warp complete (per-warp buffer)

    // stream this lane's row (bank-conflict-free: stride 68 words) through 64x16 GEMM
    {
        const float4* xr = reinterpret_cast<const float4*>(s_xz[wid] + lane * XZ_STRIDE);
        #pragma unroll
        for (int q = 0; q < 16; q++) {
            const float4 x = xr[q];
            row_fma(h, x.x, wq, 3 + 4*q);
            row_fma(h, x.y, wq, 4 + 4*q);
            row_fma(h, x.z, wq, 5 + 4*q);
            row_fma(h, x.w, wq, 6 + 4*q);
        }
    }

    float hv[H1];
    #pragma unroll
    for (int p = 0; p < 8; p++) upk2(h[p], hv[2*p], hv[2*p+1]);

    // relu + LayerNorm(16) in-lane
    float s = 0.f;
    #pragma unroll
    for (int j = 0; j < H1; j++) { hv[j] = fmaxf(hv[j], 0.f); s += hv[j]; }
    const float mu = s * (1.f / H1);
    float var = 0.f;
    #pragma unroll
    for (int j = 0; j < H1; j++) { const float d = hv[j] - mu; var += d * d; }
    const float rstd = rsqrtf(var * (1.f / H1) + EPS);

    // ln output, then sum over 32 samples (butterfly), then x2 (sum(2z)=2*sum(z))
    #pragma unroll
    for (int j = 0; j < H1; j++) {
        float y = (hv[j] - mu) * rstd * s_g1[j] + s_be1[j];
        #pragma unroll
        for (int o = 16; o > 0; o >>= 1) y += __shfl_xor_sync(FULL, y, o);
        hv[j] = y + y;                       // reuse hv as the summed vector
    }

    // --- stage 2: 16 -> 32, lane = channel (weights: coalesced global, L1-hot) ---
    float t2 = b2a[lane];
    #pragma unroll
    for (int k = 0; k < H1; k++) t2 += hv[k] * w2a[k * BASE + lane];
    t2 = fmaxf(t2, 0.f);
    const float m2 = wsum(t2) * (1.f / BASE);
    const float d2 = t2 - m2;
    const float vv2 = wsum(d2 * d2) * (1.f / BASE);
    const float z2 = d2 * rsqrtf(vv2 + EPS) * g2a[lane] + be2a[lane];

    // --- stage 3: 32 -> 32 + skip ---
    float u = b2b[lane];
    #pragma unroll
    for (int k = 0; k < BASE; k++)
        u += __shfl_sync(FULL, z2, k) * w2b[k * BASE + lane];
    u = fmaxf(u, 0.f);
    const float m3 = wsum(u) * (1.f / BASE);
    const float d3 = u - m3;
    const float vv3 = wsum(d3 * d3) * (1.f / BASE);
    const float z3 = d3 * rsqrtf(vv3 + EPS) * g2b[lane] + be2b[lane] + z2;

    // --- stage 4: 32 -> 13, tanh ---
    float o4 = 0.f;
    #pragma unroll
    for (int k = 0; k < BASE; k++) {
        const float zk = __shfl_sync(FULL, z3, k);
        if (lane < OUTD) o4 += zk * wout[k * OUTD + lane];
    }
    if (lane < OUTD)
        out[(size_t)b * OUTD + lane] = tanhf(o4 + bout[lane]);
}

extern "C" void kernel_launch(void* const* d_in, const int* in_sizes, int n_in,
                              void* d_out, int out_size) {
    (void)in_sizes; (void)n_in; (void)out_size;
    // 8192 batches, one warp each, 4 warps/block -> 2048 blocks
    plane_kernel<<<2048, WARPS_PER_BLOCK * 32>>>(
        (const float*)d_in[0],  (const float*)d_in[1],
        (const float*)d_in[2],  (const float*)d_in[3],
        (const int*)  d_in[4],  (const float*)d_in[5],
        (const float*)d_in[6],  (const float*)d_in[7],
        (const float*)d_in[8],  (const float*)d_in[9],
        (const float*)d_in[10], (const float*)d_in[11],
        (const float*)d_in[12], (const float*)d_in[13],
        (const float*)d_in[14], (const float*)d_in[15],
        (const float*)d_in[16], (const float*)d_in[17],
        (const float*)d_in[18], (const float*)d_in[19],
        (float*)d_out);
}

// round 4
// speedup vs baseline: 1.1858x; 1.1858x over previous
#include <cuda_runtime.h>
#include <cstdint>

#define FULL 0xffffffffu

constexpr int NS   = 32;
constexpr int H1   = 16;
constexpr int BASE = 32;
constexpr int OUTD = 13;
constexpr int DIN  = 79;     // 3 + 64 + 12
constexpr float EPS = 1e-6f;
constexpr int XZ_STRIDE = 68;   // 64 + 4 pad; conflict-free, 16B-aligned rows

typedef unsigned long long u64;

// ---- packed f32x2 helpers ---------------------------------------------------
__device__ __forceinline__ u64 pk2(float a, float b) {
    u64 r; asm("mov.b64 %0, {%1, %2};" : "=l"(r) : "f"(a), "f"(b)); return r;
}
__device__ __forceinline__ u64 bcast2(float a) {
    u64 r; asm("mov.b64 %0, {%1, %1};" : "=l"(r) : "f"(a)); return r;
}
__device__ __forceinline__ void upk2(u64 v, float& a, float& b) {
    asm("mov.b64 {%0, %1}, %2;" : "=f"(a), "=f"(b) : "l"(v));
}
__device__ __forceinline__ void fma2(u64& d, u64 a, u64 b) {
    asm("fma.rn.f32x2 %0, %1, %2, %0;" : "+l"(d) : "l"(a), "l"(b));
}
__device__ __forceinline__ u64 add2(u64 a, u64 b) {
    u64 r; asm("add.rn.f32x2 %0, %1, %2;" : "=l"(r) : "l"(a), "l"(b)); return r;
}

// ---- cp.async ---------------------------------------------------------------
__device__ __forceinline__ uint32_t smem_u32(const void* p) {
    return (uint32_t)__cvta_generic_to_shared(p);
}
__device__ __forceinline__ void cp16(uint32_t s, const void* g) {
    asm volatile("cp.async.cg.shared.global [%0], [%1], 16;" :: "r"(s), "l"(g));
}
__device__ __forceinline__ void cp_commit() { asm volatile("cp.async.commit_group;"); }
__device__ __forceinline__ void cp_wait0()  { asm volatile("cp.async.wait_group 0;"); }

// one weight fetch feeds BOTH batch streams: 4 LDS.128 + 16 FFMA2 per input row
__device__ __forceinline__ void row_fma2b(u64 (&h0)[8], u64 (&h1)[8],
                                          float x0, float x1,
                                          const ulonglong2* __restrict__ wq, int row) {
    u64 bx0 = bcast2(x0), bx1 = bcast2(x1);
    ulonglong2 p0 = wq[row * 4 + 0];
    ulonglong2 p1 = wq[row * 4 + 1];
    ulonglong2 p2 = wq[row * 4 + 2];
    ulonglong2 p3 = wq[row * 4 + 3];
    fma2(h0[0], bx0, p0.x); fma2(h1[0], bx1, p0.x);
    fma2(h0[1], bx0, p0.y); fma2(h1[1], bx1, p0.y);
    fma2(h0[2], bx0, p1.x); fma2(h1[2], bx1, p1.x);
    fma2(h0[3], bx0, p1.y); fma2(h1[3], bx1, p1.y);
    fma2(h0[4], bx0, p2.x); fma2(h1[4], bx1, p2.x);
    fma2(h0[5], bx0, p2.y); fma2(h1[5], bx1, p2.y);
    fma2(h0[6], bx0, p3.x); fma2(h1[6], bx1, p3.x);
    fma2(h0[7], bx0, p3.y); fma2(h1[7], bx1, p3.y);
}

__device__ __forceinline__ float wsum(float v) {
    #pragma unroll
    for (int o = 16; o > 0; o >>= 1) v += __shfl_xor_sync(FULL, v, o);
    return v;
}

struct Batch {
    float R00,R01,R02,R10,R11,R12,R20,R21,R22, px,py,pz;
    float pk0, pk1, pk2v;     // per-lane picked position
};

__device__ __forceinline__ void batch_setup(
    int b, int lane, int idx,
    const float* __restrict__ pos, const float* __restrict__ quat,
    const float* __restrict__ aabb, Batch& B)
{
    float qx = quat[4*b+0], qy = quat[4*b+1], qz = quat[4*b+2], qw = quat[4*b+3];
    const float qn = rsqrtf(qx*qx + qy*qy + qz*qz + qw*qw);
    qx *= qn; qy *= qn; qz *= qn; qw *= qn;
    B.R00 = 1.f - 2.f*(qy*qy + qz*qz); B.R01 = 2.f*(qx*qy - qz*qw); B.R02 = 2.f*(qx*qz + qy*qw);
    B.R10 = 2.f*(qx*qy + qz*qw); B.R11 = 1.f - 2.f*(qx*qx + qz*qz); B.R12 = 2.f*(qy*qz - qx*qw);
    B.R20 = 2.f*(qx*qz - qy*qw); B.R21 = 2.f*(qy*qz + qx*qw); B.R22 = 1.f - 2.f*(qx*qx + qy*qy);
    B.px = pos[3*b+0]; B.py = pos[3*b+1]; B.pz = pos[3*b+2];
    const float lo0 = aabb[6*b+0], lo1 = aabb[6*b+1], lo2 = aabb[6*b+2];
    const float sd0 = (aabb[6*b+3] - lo0) * 0.125f;
    const float sd1 = (aabb[6*b+4] - lo1) * 0.125f;
    const float sd2 = (aabb[6*b+5] - lo2) * 0.125f;
    const float c0 = (float)((idx >> 6) & 7) + 0.5f;   // meshgrid 'ij' decode
    const float c1 = (float)((idx >> 3) & 7) + 0.5f;
    const float c2 = (float)( idx       & 7) + 0.5f;
    const float v0 = c0 * sd0 + lo0;
    const float v1 = c1 * sd1 + lo1;
    const float v2 = c2 * sd2 + lo2;
    B.pk0  = B.R00*v0 + B.R01*v1 + B.R02*v2 + B.px;
    B.pk1  = B.R10*v0 + B.R11*v1 + B.R12*v2 + B.py;
    B.pk2v = B.R20*v0 + B.R21*v1 + B.R22*v2 + B.pz;
}

__global__ __launch_bounds__(64, 5) void plane_kernel(
    const float* __restrict__ pos,  const float* __restrict__ quat,
    const float* __restrict__ xz,   const float* __restrict__ aabb,
    const int*   __restrict__ widx, const float* __restrict__ pls_p,
    const float* __restrict__ w1,   const float* __restrict__ b1,
    const float* __restrict__ g1,   const float* __restrict__ be1,
    const float* __restrict__ w2a,  const float* __restrict__ b2a,
    const float* __restrict__ g2a,  const float* __restrict__ be2a,
    const float* __restrict__ w2b,  const float* __restrict__ b2b,
    const float* __restrict__ g2b,  const float* __restrict__ be2b,
    const float* __restrict__ wout, const float* __restrict__ bout,
    float* __restrict__ out)
{
    __shared__ __align__(16) float s_w1[DIN * H1];                   // 5056 B
    __shared__ float s_b1[H1], s_g1[H1], s_be1[H1];
    __shared__ __align__(16) float s_xz[2][2][NS * XZ_STRIDE];       // 2 warps x 2 batches

    const int t = threadIdx.x;
    for (int i = t; i < DIN * H1; i += 64) s_w1[i] = w1[i];
    if (t < H1) { s_b1[t] = b1[t]; s_g1[t] = g1[t]; s_be1[t] = be1[t]; }
    __syncthreads();

    const int wid  = t >> 5;
    const int lane = t & 31;
    const int b0 = (blockIdx.x * 2 + wid) * 2;
    const int b1i = b0 + 1;

    const int idx0 = widx[NS * b0  + lane];
    const int idx1 = widx[NS * b1i + lane];

    // --- coalesced gather of both batches' 32 rows via cp.async (overlaps math) ---
    {
        const uint32_t sb0 = smem_u32(&s_xz[wid][0][0]);
        const uint32_t sb1 = smem_u32(&s_xz[wid][1][0]);
        const float* x0b = xz + (size_t)b0  * 512 * 64;
        const float* x1b = xz + (size_t)b1i * 512 * 64;
        #pragma unroll
        for (int i = 0; i < 16; i++) {
            const int f  = i * 32 + lane;
            const int r  = f >> 4;
            const int c4 = f & 15;
            const int r0 = __shfl_sync(FULL, idx0, r);
            cp16(sb0 + (uint32_t)(r * XZ_STRIDE + c4 * 4) * 4, x0b + (size_t)r0 * 64 + c4 * 4);
        }
        #pragma unroll
        for (int i = 0; i < 16; i++) {
            const int f  = i * 32 + lane;
            const int r  = f >> 4;
            const int c4 = f & 15;
            const int r1 = __shfl_sync(FULL, idx1, r);
            cp16(sb1 + (uint32_t)(r * XZ_STRIDE + c4 * 4) * 4, x1b + (size_t)r1 * 64 + c4 * 4);
        }
        cp_commit();
    }

    // --- per-batch scalar math (overlaps the async gather) ---
    Batch B0, B1;
    batch_setup(b0,  lane, idx0, pos, quat, aabb, B0);
    batch_setup(b1i, lane, idx1, pos, quat, aabb, B1);
    const float es = expf(pls_p[0]);

    // pose-part of stage 1 (uniform over lanes): lanes 0..15 compute channel `lane`
    float pc0 = 0.f, pc1 = 0.f;
    if (lane < H1) {
        const float po0[12] = { B0.px*es, B0.py*es, B0.pz*es,
            B0.R00,B0.R01,B0.R02,B0.R10,B0.R11,B0.R12,B0.R20,B0.R21,B0.R22 };
        const float po1[12] = { B1.px*es, B1.py*es, B1.pz*es,
            B1.R00,B1.R01,B1.R02,B1.R10,B1.R11,B1.R12,B1.R20,B1.R21,B1.R22 };
        pc0 = s_b1[lane]; pc1 = s_b1[lane];
        #pragma unroll
        for (int m = 0; m < 12; m++) {
            const float w = s_w1[(67 + m) * H1 + lane];
            pc0 += po0[m] * w; pc1 += po1[m] * w;
        }
    }

    u64 h0[8], h1[8];
    #pragma unroll
    for (int p = 0; p < 8; p++) {
        h0[p] = pk2(__shfl_sync(FULL, pc0, 2*p), __shfl_sync(FULL, pc0, 2*p + 1));
        h1[p] = pk2(__shfl_sync(FULL, pc1, 2*p), __shfl_sync(FULL, pc1, 2*p + 1));
    }

    const ulonglong2* wq = reinterpret_cast<const ulonglong2*>(s_w1);
    row_fma2b(h0, h1, B0.pk0,  B1.pk0,  wq, 0);
    row_fma2b(h0, h1, B0.pk1,  B1.pk1,  wq, 1);
    row_fma2b(h0, h1, B0.pk2v, B1.pk2v, wq, 2);

    cp_wait0();
    __syncwarp();

    // --- stage-1 GEMM: both batches share each weight fetch ---
    {
        const float4* xr0 = reinterpret_cast<const float4*>(&s_xz[wid][0][lane * XZ_STRIDE]);
        const float4* xr1 = reinterpret_cast<const float4*>(&s_xz[wid][1][lane * XZ_STRIDE]);
        #pragma unroll
        for (int q = 0; q < 16; q++) {
            const float4 x0 = xr0[q];
            const float4 x1 = xr1[q];
            row_fma2b(h0, h1, x0.x, x1.x, wq, 3 + 4*q);
            row_fma2b(h0, h1, x0.y, x1.y, wq, 4 + 4*q);
            row_fma2b(h0, h1, x0.z, x1.z, wq, 5 + 4*q);
            row_fma2b(h0, h1, x0.w, x1.w, wq, 6 + 4*q);
        }
    }

    // --- relu + LN(16) per batch, pack (b0,b1) per channel ---
    float hv0[H1], hv1[H1];
    #pragma unroll
    for (int p = 0; p < 8; p++) { upk2(h0[p], hv0[2*p], hv0[2*p+1]);
                                  upk2(h1[p], hv1[2*p], hv1[2*p+1]); }
    float s0 = 0.f, s1 = 0.f;
    #pragma unroll
    for (int j = 0; j < H1; j++) {
        hv0[j] = fmaxf(hv0[j], 0.f); s0 += hv0[j];
        hv1[j] = fmaxf(hv1[j], 0.f); s1 += hv1[j];
    }
    const float mu0 = s0 * (1.f/H1), mu1 = s1 * (1.f/H1);
    float va0 = 0.f, va1 = 0.f;
    #pragma unroll
    for (int j = 0; j < H1; j++) {
        float d0 = hv0[j]-mu0, d1 = hv1[j]-mu1; va0 += d0*d0; va1 += d1*d1;
    }
    const float rs0 = rsqrtf(va0*(1.f/H1) + EPS);
    const float rs1 = rsqrtf(va1*(1.f/H1) + EPS);

    u64 Y[16];
    #pragma unroll
    for (int j = 0; j < H1; j++) {
        const float y0 = (hv0[j]-mu0)*rs0*s_g1[j] + s_be1[j];
        const float y1 = (hv1[j]-mu1)*rs1*s_g1[j] + s_be1[j];
        Y[j] = pk2(y0, y1);
    }

    // --- fold reduction over 32 lanes: 16 u64 -> 1 u64/lane; lane 2k holds ch k ---
    u64 A[8];
    { const bool lo = (lane & 16) == 0;
      #pragma unroll
      for (int i = 0; i < 8; i++) {
          u64 snd = lo ? Y[8+i] : Y[i];
          A[i] = add2(lo ? Y[i] : Y[8+i], __shfl_xor_sync(FULL, snd, 16)); } }
    u64 Bv[4];
    { const bool lo = (lane & 8) == 0;
      #pragma unroll
      for (int i = 0; i < 4; i++) {
          u64 snd = lo ? A[4+i] : A[i];
          Bv[i] = add2(lo ? A[i] : A[4+i], __shfl_xor_sync(FULL, snd, 8)); } }
    u64 Cv[2];
    { const bool lo = (lane & 4) == 0;
      #pragma unroll
      for (int i = 0; i < 2; i++) {
          u64 snd = lo ? Cv[0] : Cv[0]; // placeholder avoided below
          (void)snd;
          u64 sv = lo ? Bv[2+i] : Bv[i];
          Cv[i] = add2(lo ? Bv[i] : Bv[2+i], __shfl_xor_sync(FULL, sv, 4)); } }
    u64 Dv;
    { const bool lo = (lane & 2) == 0;
      u64 sv = lo ? Cv[1] : Cv[0];
      Dv = add2(lo ? Cv[0] : Cv[1], __shfl_xor_sync(FULL, sv, 2)); }
    u64 S = add2(Dv, __shfl_xor_sync(FULL, Dv, 1));
    S = add2(S, S);                                  // z = z + z before the sum

    // --- stage 2: 16 -> 32 (lane = channel), weight loads shared across batches ---
    float t20 = b2a[lane], t21 = t20;
    #pragma unroll
    for (int k = 0; k < H1; k++) {
        u64 a = __shfl_sync(FULL, S, 2*k);
        float a0, a1; upk2(a, a0, a1);
        const float w = w2a[k * BASE + lane];
        t20 += a0 * w; t21 += a1 * w;
    }
    t20 = fmaxf(t20, 0.f); t21 = fmaxf(t21, 0.f);
    const float m20 = wsum(t20)*(1.f/BASE), m21 = wsum(t21)*(1.f/BASE);
    const float d20 = t20 - m20, d21 = t21 - m21;
    const float v20 = wsum(d20*d20)*(1.f/BASE), v21 = wsum(d21*d21)*(1.f/BASE);
    const float ga = g2a[lane], ba = be2a[lane];
    const float z20 = d20*rsqrtf(v20+EPS)*ga + ba;
    const float z21 = d21*rsqrtf(v21+EPS)*ga + ba;

    // --- stage 3: 32 -> 32 + skip ---
    float u0 = b2b[lane], u1 = u0;
    #pragma unroll
    for (int k = 0; k < BASE; k++) {
        const float w = w2b[k * BASE + lane];
        u0 += __shfl_sync(FULL, z20, k) * w;
        u1 += __shfl_sync(FULL, z21, k) * w;
    }
    u0 = fmaxf(u0, 0.f); u1 = fmaxf(u1, 0.f);
    const float m30 = wsum(u0)*(1.f/BASE), m31 = wsum(u1)*(1.f/BASE);
    const float d30 = u0 - m30, d31 = u1 - m31;
    const float v30 = wsum(d30*d30)*(1.f/BASE), v31 = wsum(d31*d31)*(1.f/BASE);
    const float gb = g2b[lane], bb = be2b[lane];
    const float z30 = d30*rsqrtf(v30+EPS)*gb + bb + z20;
    const float z31 = d31*rsqrtf(v31+EPS)*gb + bb + z21;

    // --- stage 4: 32 -> 13, tanh ---
    float o0 = 0.f, o1 = 0.f;
    #pragma unroll
    for (int k = 0; k < BASE; k++) {
        const float zk0 = __shfl_sync(FULL, z30, k);
        const float zk1 = __shfl_sync(FULL, z31, k);
        if (lane < OUTD) {
            const float w = wout[k * OUTD + lane];
            o0 += zk0 * w; o1 += zk1 * w;
        }
    }
    if (lane < OUTD) {
        const float bo = bout[lane];
        out[(size_t)b0  * OUTD + lane] = tanhf(o0 + bo);
        out[(size_t)b1i * OUTD + lane] = tanhf(o1 + bo);
    }
}

extern "C" void kernel_launch(void* const* d_in, const int* in_sizes, int n_in,
                              void* d_out, int out_size) {
    (void)in_sizes; (void)n_in; (void)out_size;
    // 8192 batches, 2 per warp, 2 warps/block -> 2048 blocks of 64 threads
    plane_kernel<<<2048, 64>>>(
        (const float*)d_in[0],  (const float*)d_in[1],
        (const float*)d_in[2],  (const float*)d_in[3],
        (const int*)  d_in[4],  (const float*)d_in[5],
        (const float*)d_in[6],  (const float*)d_in[7],
        (const float*)d_in[8],  (const float*)d_in[9],
        (const float*)d_in[10], (const float*)d_in[11],
        (const float*)d_in[12], (const float*)d_in[13],
        (const float*)d_in[14], (const float*)d_in[15],
        (const float*)d_in[16], (const float*)d_in[17],
        (const float*)d_in[18], (const float*)d_in[19],
        (float*)d_out);
}

// round 12
// speedup vs baseline: 1.3524x; 1.1405x over previous
#include <cuda_runtime.h>
#include <cuda_fp16.h>
#include <cstdint>

#define FULL 0xffffffffu

constexpr int NS   = 32;
constexpr int H1   = 16;
constexpr int BASE = 32;
constexpr int OUTD = 13;
constexpr int DIN  = 79;     // 3 + 64 + 12
constexpr float EPS = 1e-6f;
// halfs per staged row: 64 data + 8 pad = 144 B -> 16B-aligned rows AND
// conflict-free LDS.128 (36 words/row; 36 mod 32 = 4 -> distinct banks per phase)
constexpr int XZ_H_STRIDE = 72;

typedef unsigned long long u64;

// ---- packed f32x2 helpers ---------------------------------------------------
__device__ __forceinline__ u64 pk2(float a, float b) {
    u64 r; asm("mov.b64 %0, {%1, %2};" : "=l"(r) : "f"(a), "f"(b)); return r;
}
__device__ __forceinline__ u64 bcast2(float a) {
    u64 r; asm("mov.b64 %0, {%1, %1};" : "=l"(r) : "f"(a)); return r;
}
__device__ __forceinline__ void upk2(u64 v, float& a, float& b) {
    asm("mov.b64 {%0, %1}, %2;" : "=f"(a), "=f"(b) : "l"(v));
}
__device__ __forceinline__ void fma2(u64& d, u64 a, u64 b) {
    asm("fma.rn.f32x2 %0, %1, %2, %0;" : "+l"(d) : "l"(a), "l"(b));
}
__device__ __forceinline__ u64 add2(u64 a, u64 b) {
    u64 r; asm("add.rn.f32x2 %0, %1, %2;" : "=l"(r) : "l"(a), "l"(b)); return r;
}

// one weight fetch feeds BOTH batch streams
__device__ __forceinline__ void row_fma2b(u64 (&h0)[8], u64 (&h1)[8],
                                          float x0, float x1,
                                          const ulonglong2* __restrict__ wq, int row) {
    u64 bx0 = bcast2(x0), bx1 = bcast2(x1);
    ulonglong2 p0 = wq[row * 4 + 0];
    ulonglong2 p1 = wq[row * 4 + 1];
    ulonglong2 p2 = wq[row * 4 + 2];
    ulonglong2 p3 = wq[row * 4 + 3];
    fma2(h0[0], bx0, p0.x); fma2(h1[0], bx1, p0.x);
    fma2(h0[1], bx0, p0.y); fma2(h1[1], bx1, p0.y);
    fma2(h0[2], bx0, p1.x); fma2(h1[2], bx1, p1.x);
    fma2(h0[3], bx0, p1.y); fma2(h1[3], bx1, p1.y);
    fma2(h0[4], bx0, p2.x); fma2(h1[4], bx1, p2.x);
    fma2(h0[5], bx0, p2.y); fma2(h1[5], bx1, p2.y);
    fma2(h0[6], bx0, p3.x); fma2(h1[6], bx1, p3.x);
    fma2(h0[7], bx0, p3.y); fma2(h1[7], bx1, p3.y);
}

// fused (sum, sumsq) butterfly over 32 lanes on a packed f32x2
__device__ __forceinline__ u64 wred2(u64 v) {
    #pragma unroll
    for (int o = 16; o > 0; o >>= 1) v = add2(v, __shfl_xor_sync(FULL, v, o));
    return v;
}

struct Batch {
    float R00,R01,R02,R10,R11,R12,R20,R21,R22, px,py,pz;
    float pk0, pk1, pk2v;
};

__device__ __forceinline__ void batch_setup(
    int b, int idx,
    const float* __restrict__ pos, const float* __restrict__ quat,
    const float* __restrict__ aabb, Batch& B)
{
    float qx = quat[4*b+0], qy = quat[4*b+1], qz = quat[4*b+2], qw = quat[4*b+3];
    const float qn = rsqrtf(qx*qx + qy*qy + qz*qz + qw*qw);
    qx *= qn; qy *= qn; qz *= qn; qw *= qn;
    B.R00 = 1.f - 2.f*(qy*qy + qz*qz); B.R01 = 2.f*(qx*qy - qz*qw); B.R02 = 2.f*(qx*qz + qy*qw);
    B.R10 = 2.f*(qx*qy + qz*qw); B.R11 = 1.f - 2.f*(qx*qx + qz*qz); B.R12 = 2.f*(qy*qz - qx*qw);
    B.R20 = 2.f*(qx*qz - qy*qw); B.R21 = 2.f*(qy*qz + qx*qw); B.R22 = 1.f - 2.f*(qx*qx + qy*qy);
    B.px = pos[3*b+0]; B.py = pos[3*b+1]; B.pz = pos[3*b+2];
    const float lo0 = aabb[6*b+0], lo1 = aabb[6*b+1], lo2 = aabb[6*b+2];
    const float sd0 = (aabb[6*b+3] - lo0) * 0.125f;
    const float sd1 = (aabb[6*b+4] - lo1) * 0.125f;
    const float sd2 = (aabb[6*b+5] - lo2) * 0.125f;
    const float c0 = (float)((idx >> 6) & 7) + 0.5f;   // meshgrid 'ij' decode
    const float c1 = (float)((idx >> 3) & 7) + 0.5f;
    const float c2 = (float)( idx       & 7) + 0.5f;
    const float v0 = c0 * sd0 + lo0;
    const float v1 = c1 * sd1 + lo1;
    const float v2 = c2 * sd2 + lo2;
    B.pk0  = B.R00*v0 + B.R01*v1 + B.R02*v2 + B.px;
    B.pk1  = B.R10*v0 + B.R11*v1 + B.R12*v2 + B.py;
    B.pk2v = B.R20*v0 + B.R21*v1 + B.R22*v2 + B.pz;
}

__global__ __launch_bounds__(64, 8) void plane_kernel(
    const float* __restrict__ pos,  const float* __restrict__ quat,
    const float* __restrict__ xz,   const float* __restrict__ aabb,
    const int*   __restrict__ widx, const float* __restrict__ pls_p,
    const float* __restrict__ w1,   const float* __restrict__ b1,
    const float* __restrict__ g1,   const float* __restrict__ be1,
    const float* __restrict__ w2a,  const float* __restrict__ b2a,
    const float* __restrict__ g2a,  const float* __restrict__ be2a,
    const float* __restrict__ w2b,  const float* __restrict__ b2b,
    const float* __restrict__ g2b,  const float* __restrict__ be2b,
    const float* __restrict__ wout, const float* __restrict__ bout,
    float* __restrict__ out)
{
    __shared__ __align__(16) float s_w1[DIN * H1];                   // 5056 B
    __shared__ float s_b1[H1], s_g1[H1], s_be1[H1];
    // fp16 staging: 2 warps x 2 batches x 32 rows x 72 halfs = 18432 B
    __shared__ __align__(16) __half s_xz[2][2][NS * XZ_H_STRIDE];

    const int t = threadIdx.x;
    for (int i = t; i < DIN * H1; i += 64) s_w1[i] = w1[i];
    if (t < H1) { s_b1[t] = b1[t]; s_g1[t] = g1[t]; s_be1[t] = be1[t]; }
    __syncthreads();

    const int wid  = t >> 5;
    const int lane = t & 31;
    const int b0  = (blockIdx.x * 2 + wid) * 2;
    const int b1i = b0 + 1;

    const int idx0 = widx[NS * b0  + lane];
    const int idx1 = widx[NS * b1i + lane];

    // --- coalesced gather (LDG.128 -> cvt fp16 -> STS.64), issued first for MLP ---
    {
        __half* buf0 = &s_xz[wid][0][0];
        __half* buf1 = &s_xz[wid][1][0];
        const float* x0b = xz + (size_t)b0  * 512 * 64;
        const float* x1b = xz + (size_t)b1i * 512 * 64;
        #pragma unroll
        for (int i = 0; i < 16; i++) {
            const int f  = i * 32 + lane;
            const int r  = f >> 4;              // row 0..31
            const int c4 = f & 15;              // float4 column
            const int r0 = __shfl_sync(FULL, idx0, r);
            const float4 v = *(reinterpret_cast<const float4*>(x0b + (size_t)r0 * 64) + c4);
            __half2 h01 = __floats2half2_rn(v.x, v.y);
            __half2 h23 = __floats2half2_rn(v.z, v.w);
            *reinterpret_cast<__half2*>(buf0 + r * XZ_H_STRIDE + c4 * 4)     = h01;
            *reinterpret_cast<__half2*>(buf0 + r * XZ_H_STRIDE + c4 * 4 + 2) = h23;
        }
        #pragma unroll
        for (int i = 0; i < 16; i++) {
            const int f  = i * 32 + lane;
            const int r  = f >> 4;
            const int c4 = f & 15;
            const int r1 = __shfl_sync(FULL, idx1, r);
            const float4 v = *(reinterpret_cast<const float4*>(x1b + (size_t)r1 * 64) + c4);
            __half2 h01 = __floats2half2_rn(v.x, v.y);
            __half2 h23 = __floats2half2_rn(v.z, v.w);
            *reinterpret_cast<__half2*>(buf1 + r * XZ_H_STRIDE + c4 * 4)     = h01;
            *reinterpret_cast<__half2*>(buf1 + r * XZ_H_STRIDE + c4 * 4 + 2) = h23;
        }
    }

    // --- per-batch scalar math (overlaps gather loads) ---
    Batch B0, B1;
    batch_setup(b0,  idx0, pos, quat, aabb, B0);
    batch_setup(b1i, idx1, pos, quat, aabb, B1);
    const float es = expf(pls_p[0]);

    float pc0 = 0.f, pc1 = 0.f;
    if (lane < H1) {
        const float po0[12] = { B0.px*es, B0.py*es, B0.pz*es,
            B0.R00,B0.R01,B0.R02,B0.R10,B0.R11,B0.R12,B0.R20,B0.R21,B0.R22 };
        const float po1[12] = { B1.px*es, B1.py*es, B1.pz*es,
            B1.R00,B1.R01,B1.R02,B1.R10,B1.R11,B1.R12,B1.R20,B1.R21,B1.R22 };
        pc0 = s_b1[lane]; pc1 = s_b1[lane];
        #pragma unroll
        for (int m = 0; m < 12; m++) {
            const float w = s_w1[(67 + m) * H1 + lane];
            pc0 += po0[m] * w; pc1 += po1[m] * w;
        }
    }

    u64 h0[8], h1[8];
    #pragma unroll
    for (int p = 0; p < 8; p++) {
        h0[p] = pk2(__shfl_sync(FULL, pc0, 2*p), __shfl_sync(FULL, pc0, 2*p + 1));
        h1[p] = pk2(__shfl_sync(FULL, pc1, 2*p), __shfl_sync(FULL, pc1, 2*p + 1));
    }

    const ulonglong2* wq = reinterpret_cast<const ulonglong2*>(s_w1);
    row_fma2b(h0, h1, B0.pk0,  B1.pk0,  wq, 0);
    row_fma2b(h0, h1, B0.pk1,  B1.pk1,  wq, 1);
    row_fma2b(h0, h1, B0.pk2v, B1.pk2v, wq, 2);

    __syncwarp();   // per-warp staging buffers complete

    // --- stage-1 GEMM: LDS.128 (16B-aligned: lane*144B) x 8 iters per buffer ---
    {
        const uint4* xr0 = reinterpret_cast<const uint4*>(&s_xz[wid][0][lane * XZ_H_STRIDE]);
        const uint4* xr1 = reinterpret_cast<const uint4*>(&s_xz[wid][1][lane * XZ_H_STRIDE]);
        #pragma unroll
        for (int q = 0; q < 8; q++) {
            const uint4 u0 = xr0[q];
            const uint4 u1 = xr1[q];
            const __half2* p0 = reinterpret_cast<const __half2*>(&u0);
            const __half2* p1 = reinterpret_cast<const __half2*>(&u1);
            #pragma unroll
            for (int m = 0; m < 4; m++) {
                const float2 f0 = __half22float2(p0[m]);
                const float2 f1 = __half22float2(p1[m]);
                row_fma2b(h0, h1, f0.x, f1.x, wq, 3 + 8*q + 2*m);
                row_fma2b(h0, h1, f0.y, f1.y, wq, 4 + 8*q + 2*m);
            }
        }
    }

    // --- relu + LN(16) per batch (in-lane) ---
    float hv0[H1], hv1[H1];
    #pragma unroll
    for (int p = 0; p < 8; p++) { upk2(h0[p], hv0[2*p], hv0[2*p+1]);
                                  upk2(h1[p], hv1[2*p], hv1[2*p+1]); }
    float s0 = 0.f, s1 = 0.f;
    #pragma unroll
    for (int j = 0; j < H1; j++) {
        hv0[j] = fmaxf(hv0[j], 0.f); s0 += hv0[j];
        hv1[j] = fmaxf(hv1[j], 0.f); s1 += hv1[j];
    }
    const float mu0 = s0 * (1.f/H1), mu1 = s1 * (1.f/H1);
    float va0 = 0.f, va1 = 0.f;
    #pragma unroll
    for (int j = 0; j < H1; j++) {
        float d0 = hv0[j]-mu0, d1 = hv1[j]-mu1; va0 += d0*d0; va1 += d1*d1;
    }
    const float rs0 = rsqrtf(va0*(1.f/H1) + EPS);
    const float rs1 = rsqrtf(va1*(1.f/H1) + EPS);

    u64 Y[16];
    #pragma unroll
    for (int j = 0; j < H1; j++) {
        Y[j] = pk2((hv0[j]-mu0)*rs0*s_g1[j] + s_be1[j],
                   (hv1[j]-mu1)*rs1*s_g1[j] + s_be1[j]);
    }

    // --- fold reduction over 32 lanes: lane 2k ends holding channel k sum ---
    u64 A[8];
    { const bool lo = (lane & 16) == 0;
      #pragma unroll
      for (int i = 0; i < 8; i++) {
          u64 snd = lo ? Y[8+i] : Y[i];
          A[i] = add2(lo ? Y[i] : Y[8+i], __shfl_xor_sync(FULL, snd, 16)); } }
    u64 Bv[4];
    { const bool lo = (lane & 8) == 0;
      #pragma unroll
      for (int i = 0; i < 4; i++) {
          u64 snd = lo ? A[4+i] : A[i];
          Bv[i] = add2(lo ? A[i] : A[4+i], __shfl_xor_sync(FULL, snd, 8)); } }
    u64 Cv[2];
    { const bool lo = (lane & 4) == 0;
      #pragma unroll
      for (int i = 0; i < 2; i++) {
          u64 sv = lo ? Bv[2+i] : Bv[i];
          Cv[i] = add2(lo ? Bv[i] : Bv[2+i], __shfl_xor_sync(FULL, sv, 4)); } }
    u64 Dv;
    { const bool lo = (lane & 2) == 0;
      u64 sv = lo ? Cv[1] : Cv[0];
      Dv = add2(lo ? Cv[0] : Cv[1], __shfl_xor_sync(FULL, sv, 2)); }
    u64 S = add2(Dv, __shfl_xor_sync(FULL, Dv, 1));
    S = add2(S, S);                                  // z = z + z commuted past the sum

    // --- stage 2: 16 -> 32 (lane = channel) ---
    float t20 = b2a[lane], t21 = t20;
    #pragma unroll
    for (int k = 0; k < H1; k++) {
        u64 a = __shfl_sync(FULL, S, 2*k);
        float a0, a1; upk2(a, a0, a1);
        const float w = w2a[k * BASE + lane];
        t20 += a0 * w; t21 += a1 * w;
    }
    t20 = fmaxf(t20, 0.f); t21 = fmaxf(t21, 0.f);
    // fused (sum, sumsq) reductions, independent chains
    u64 r20 = wred2(pk2(t20, t20 * t20));
    u64 r21 = wred2(pk2(t21, t21 * t21));
    float sA, sqA, sB, sqB;
    upk2(r20, sA, sqA); upk2(r21, sB, sqB);
    const float m20 = sA * (1.f/BASE), m21 = sB * (1.f/BASE);
    const float v20 = sqA * (1.f/BASE) - m20*m20;
    const float v21 = sqB * (1.f/BASE) - m21*m21;
    const float ga = g2a[lane], ba = be2a[lane];
    const float z20 = (t20 - m20)*rsqrtf(v20+EPS)*ga + ba;
    const float z21 = (t21 - m21)*rsqrtf(v21+EPS)*ga + ba;

    // --- stage 3: 32 -> 32 + skip ---
    float u0 = b2b[lane], u1 = u0;
    #pragma unroll
    for (int k = 0; k < BASE; k++) {
        const float w = w2b[k * BASE + lane];
        u0 += __shfl_sync(FULL, z20, k) * w;
        u1 += __shfl_sync(FULL, z21, k) * w;
    }
    u0 = fmaxf(u0, 0.f); u1 = fmaxf(u1, 0.f);
    u64 r30 = wred2(pk2(u0, u0 * u0));
    u64 r31 = wred2(pk2(u1, u1 * u1));
    float sC, sqC, sD, sqD;
    upk2(r30, sC, sqC); upk2(r31, sD, sqD);
    const float m30 = sC * (1.f/BASE), m31 = sD * (1.f/BASE);
    const float v30 = sqC * (1.f/BASE) - m30*m30;
    const float v31 = sqD * (1.f/BASE) - m31*m31;
    const float gb = g2b[lane], bb = be2b[lane];
    const float z30 = (u0 - m30)*rsqrtf(v30+EPS)*gb + bb + z20;
    const float z31 = (u1 - m31)*rsqrtf(v31+EPS)*gb + bb + z21;

    // --- stage 4: 32 -> 13, tanh ---
    float o0 = 0.f, o1 = 0.f;
    #pragma unroll
    for (int k = 0; k < BASE; k++) {
        const float zk0 = __shfl_sync(FULL, z30, k);
        const float zk1 = __shfl_sync(FULL, z31, k);
        if (lane < OUTD) {
            const float w = wout[k * OUTD + lane];
            o0 += zk0 * w; o1 += zk1 * w;
        }
    }
    if (lane < OUTD) {
        const float bo = bout[lane];
        out[(size_t)b0  * OUTD + lane] = tanhf(o0 + bo);
        out[(size_t)b1i * OUTD + lane] = tanhf(o1 + bo);
    }
}

extern "C" void kernel_launch(void* const* d_in, const int* in_sizes, int n_in,
                              void* d_out, int out_size) {
    (void)in_sizes; (void)n_in; (void)out_size;
    // 8192 batches, 2 per warp, 2 warps/block -> 2048 blocks of 64 threads
    plane_kernel<<<2048, 64>>>(
        (const float*)d_in[0],  (const float*)d_in[1],
        (const float*)d_in[2],  (const float*)d_in[3],
        (const int*)  d_in[4],  (const float*)d_in[5],
        (const float*)d_in[6],  (const float*)d_in[7],
        (const float*)d_in[8],  (const float*)d_in[9],
        (const float*)d_in[10], (const float*)d_in[11],
        (const float*)d_in[12], (const float*)d_in[13],
        (const float*)d_in[14], (const float*)d_in[15],
        (const float*)d_in[16], (const float*)d_in[17],
        (const float*)d_in[18], (const float*)d_in[19],
        (float*)d_out);
}